// round 16
// baseline (speedup 1.0000x reference)
#include <cuda_runtime.h>
#include <cuda_fp16.h>
#include <cstdint>
#include <math.h>

#define B_   16
#define C_   192
#define H_   128
#define W_   128
#define NF_  192
#define O4_  768
#define KALL 768
#define NCH  9                 // U chunks per step (recurrent kernel)
#define NTHREADS 288
#define HW_  (H_ * W_)
#define GRIDN 96
#define TOTR (H_ * NCH)        // 1152

#if defined(__CUDA_ARCH_FEAT_SM103_ALL) || defined(__CUDA_ARCH_FEAT_SM100_ALL) || defined(__CUDA_ARCH_FEAT_SM101_ALL)
#define TC05 1
#else
#define TC05 0
#endif

// ---- persistent device scratch ----
__device__ __align__(1024) __half g_Wt[6 * 12 * 8192];               // A tiles fp16 (16KB; 0-2 x, 3-11 U)
__device__ __align__(1024) __half g_xt[(size_t)B_ * H_ * 3 * 16384]; // x B-tiles hi|lo (32KB)
__device__ float g_Wf[O4_ * KALL];                                    // fallback weights
// h B-tiles, pre-swizzled, tau-shifted: [parity][b][tau][cb] (hi 16K | lo 16K)
__device__ __align__(1024) char g_bt[2][B_][3][3][32768];
// precomputed input-to-state: [b][t][mt][row(128)][w(128)] fp32
__device__ __align__(1024) float g_i2s[(size_t)B_ * H_ * 6 * 16384];
__device__ volatile unsigned g_cnt = 0;
__device__ volatile unsigned g_gen = 0;

// ------------------- helpers -------------------
static __device__ __forceinline__ uint32_t smem_u32(const void* p) {
    uint32_t a;
    asm("{ .reg .u64 t; cvta.to.shared.u64 t, %1; cvt.u32.u64 %0, t; }" : "=r"(a) : "l"(p));
    return a;
}
static __device__ __forceinline__ uint32_t pack_h2(__half a, __half b) {
    return (uint32_t)__half_as_ushort(a) | ((uint32_t)__half_as_ushort(b) << 16);
}
static __device__ __forceinline__ float fast_tanh(float x) {
    return 1.0f - 2.0f / (__expf(2.0f * x) + 1.0f);
}
#define SW128(o) ((uint32_t)(o) ^ ((((uint32_t)(o)) >> 3) & 0x70u))

static __device__ __forceinline__ void grid_sync() {   // fallback path only
    __syncthreads();
    if (threadIdx.x == 0) {
        __threadfence();
        unsigned gen = g_gen;
        if (atomicAdd((unsigned*)&g_cnt, 1u) == GRIDN - 1u) {
            g_cnt = 0;
            __threadfence();
            g_gen = gen + 1u;
        } else {
            while (g_gen == gen) { __nanosleep(32); }
            __threadfence();
        }
    }
    __syncthreads();
}

// ------------------- prep kernels -------------------
__global__ void prep_weights(const float* __restrict__ Wf, const float* __restrict__ Uf) {
    int idx = blockIdx.x * blockDim.x + threadIdx.x;
    if (idx >= 6 * 128 * KALL) return;
    int mt = idx / (128 * KALL);
    int m  = (idx / KALL) % 128;
    int k  = idx % KALL;
    int row = mt * 128 + m;
    int co = row >> 2, g = row & 3;
    int o = g * NF_ + co;
    int cc = k >> 6, kl = k & 63;
    float v;
    if (k < C_) {
        v = Wf[o * C_ + k];
        if ((o < 64 && k >= 64) || (o >= 64 && o < 128 && k >= 128)) v = 0.0f;
    } else {
        int q = cc - 3;
        int tau = q / 3;
        int cb = q - 3 * tau;
        int c = cb * 64 + kl;
        v = Uf[(o * NF_ + c) * 3 + tau];
    }
    g_Wf[row * KALL + k] = v;
    __half vh = __float2half_rn(v);
    size_t tile_base = (size_t)(mt * 12 + cc) * 8192;
    uint32_t swoff = SW128((uint32_t)(m * 128 + kl * 2));
    *(__half*)((char*)(g_Wt + tile_base) + swoff) = vh;
}

__global__ void prep_x(const float* __restrict__ x) {
    int id = blockIdx.x * blockDim.x + threadIdx.x;
    if (id >= B_ * H_ * 3 * 1024) return;
    int tile = id >> 10;
    int inner = id & 1023;
    int oct = inner >> 7;
    int w = inner & 127;
    int cc = tile % 3;
    int t = (tile / 3) % H_;
    int b = tile / (3 * H_);
    __half hh[8], hl[8];
    #pragma unroll
    for (int j = 0; j < 8; ++j) {
        int c = cc * 64 + oct * 8 + j;
        float v = x[((size_t)(b * C_ + c) * H_ + t) * W_ + w];
        hh[j] = __float2half_rn(v);
        hl[j] = __float2half_rn(v - __half2float(hh[j]));
    }
    size_t tb = (size_t)tile * 16384;
    uint32_t swoff = SW128((uint32_t)(w * 128 + oct * 16));
    *(uint4*)((char*)(g_xt + tb) + swoff) =
        make_uint4(pack_h2(hh[0], hh[1]), pack_h2(hh[2], hh[3]),
                   pack_h2(hh[4], hh[5]), pack_h2(hh[6], hh[7]));
    *(uint4*)((char*)(g_xt + tb + 8192) + swoff) =
        make_uint4(pack_h2(hl[0], hl[1]), pack_h2(hl[2], hl[3]),
                   pack_h2(hl[4], hl[5]), pack_h2(hl[6], hl[7]));
}

__global__ void zero_bt() {
    size_t n = sizeof(g_bt) / 16;
    uint4* p = reinterpret_cast<uint4*>(&g_bt[0][0][0][0][0]);
    size_t gidx = (size_t)blockIdx.x * blockDim.x + threadIdx.x;
    for (size_t i = gidx; i < n; i += (size_t)gridDim.x * blockDim.x)
        p[i] = make_uint4(0, 0, 0, 0);
    if (gidx == 0) { g_cnt = 0; g_gen = 0; }
}

__global__ void fill_bt(const float* __restrict__ ih) {
    int idx = blockIdx.x * blockDim.x + threadIdx.x;
    if (idx >= B_ * 3 * NF_ * W_) return;
    int w = idx & 127;
    int c = (idx >> 7) % NF_;
    int tau = (idx >> 7) / NF_ % 3;
    int b = idx / (3 * NF_ * W_);
    int r = w + 1 - tau;
    if (r < 0 || r >= 128) return;
    float v = ih[c * W_ + w];
    __half vh = __float2half_rn(v);
    __half vl = __float2half_rn(v - __half2float(vh));
    int cb = c >> 6;
    char* tbase = g_bt[0][b][tau][cb];
    uint32_t off = SW128((uint32_t)(r * 128 + 2 * (c & 63)));
    *(__half*)(tbase + off) = vh;
    *(__half*)(tbase + 16384 + off) = vl;
}

// ------------------- TC05 machinery -------------------
#if TC05
static __device__ __forceinline__ void mbar_wait(uint32_t mbar, uint32_t parity) {
    asm volatile(
        "{\n\t.reg .pred P;\n\t"
        "WL_%=:\n\t"
        "mbarrier.try_wait.parity.acquire.cta.shared::cta.b64 P, [%0], %1, 0x989680;\n\t"
        "@P bra.uni WD_%=;\n\t"
        "bra.uni WL_%=;\n\t"
        "WD_%=:\n\t}"
        :: "r"(mbar), "r"(parity) : "memory");
}
static __device__ __forceinline__ void mma_f16_ss(uint32_t d, uint64_t da, uint64_t db,
                                                  uint32_t idesc, uint32_t en) {
    asm volatile(
        "{\n\t.reg .pred p;\n\t"
        "setp.ne.u32 p, %4, 0;\n\t"
        "tcgen05.mma.cta_group::1.kind::f16 [%0], %1, %2, %3, {%5, %5, %5, %5}, p;\n\t"
        "}"
        :: "r"(d), "l"(da), "l"(db), "r"(idesc), "r"(en), "r"(0u) : "memory");
}
static __device__ __forceinline__ void tc_commit(uint32_t mbar) {
    asm volatile("tcgen05.commit.cta_group::1.mbarrier::arrive::one.shared::cluster.b64 [%0];"
                 :: "r"(mbar) : "memory");
}
static __device__ __forceinline__ void bulk_cp(uint32_t dst, const void* src, uint32_t bytes,
                                               uint32_t mbar) {
    asm volatile(
        "cp.async.bulk.shared::cluster.global.mbarrier::complete_tx::bytes [%0], [%1], %2, [%3];"
        :: "r"(dst), "l"(src), "r"(bytes), "r"(mbar) : "memory");
}
static __device__ __forceinline__ void expect_tx(uint32_t mbar, uint32_t bytes) {
    asm volatile("mbarrier.arrive.expect_tx.shared.b64 _, [%0], %1;"
                 :: "r"(mbar), "r"(bytes) : "memory");
}
static __device__ __forceinline__ void arrive_local(uint32_t mbar) {
    asm volatile("mbarrier.arrive.shared.b64 _, [%0];" :: "r"(mbar) : "memory");
}
#define LDTM_X16(r, addr) \
    asm volatile( \
        "tcgen05.ld.sync.aligned.32x32b.x16.b32 " \
        "{%0, %1, %2, %3, %4, %5, %6, %7, " \
        " %8, %9, %10, %11, %12, %13, %14, %15}, [%16];" \
        : "=r"((r)[0]),  "=r"((r)[1]),  "=r"((r)[2]),  "=r"((r)[3]), \
          "=r"((r)[4]),  "=r"((r)[5]),  "=r"((r)[6]),  "=r"((r)[7]), \
          "=r"((r)[8]),  "=r"((r)[9]),  "=r"((r)[10]), "=r"((r)[11]), \
          "=r"((r)[12]), "=r"((r)[13]), "=r"((r)[14]), "=r"((r)[15]) \
        : "r"(addr))

static constexpr uint64_t DESC_BASE_SW128 =
    (uint64_t(2) << 61) | (uint64_t(1) << 46) | (uint64_t(64) << 32) | (uint64_t(1) << 16);
#define MKDESC(a) (DESC_BASE_SW128 | ((uint64_t)(((uint32_t)(a)) >> 4) & 0x3FFFull))
#define IDESC_F16 ((1u << 4) | (16u << 17) | (8u << 24))
#endif

#define EPI_BAR() asm volatile("bar.sync 1, 256;" ::: "memory")

// ===================== i2s precompute GEMM =====================
// grid (6,16,4): rows mt, batch b, t in [tq*32, tq*32+32)
#define I2S_BUF 49152                 // A 16K | Bh 16K | Bl 16K
#define I2S_EPI (3 * I2S_BUF)
#define I2S_DSMEM (1024 + 3 * I2S_BUF + 16896)

__global__ void __launch_bounds__(NTHREADS, 1)
i2s_gemm()
{
#if TC05
    extern __shared__ __align__(16) char dsm[];
    const int tid = threadIdx.x;
    const int wid = tid >> 5;
    const int lane = tid & 31;
    const int mt = blockIdx.x;
    const int b  = blockIdx.y;
    const int tq = blockIdx.z;

    const uint32_t raw = smem_u32(dsm);
    const uint32_t dbase = (raw + 1023u) & ~1023u;
    char* dptr = dsm + (dbase - raw);

    __shared__ uint32_t s_tmem;
    __shared__ __align__(8) uint64_t s_mbar[8];   // ab0..2, mm0..2, sbar, eb
    if (wid == 8) {
        asm volatile("tcgen05.alloc.cta_group::1.sync.aligned.shared::cta.b32 [%0], %1;"
                     :: "r"(smem_u32(&s_tmem)), "r"(128u) : "memory");
    }
    if (tid == 0) {
        #pragma unroll
        for (int i = 0; i < 8; ++i)
            asm volatile("mbarrier.init.shared.b64 [%0], 1;"
                         :: "r"(smem_u32(&s_mbar[i])) : "memory");
    }
    __syncthreads();
    const uint32_t tmem = s_tmem;
    uint32_t ab[3], mm[3];
    #pragma unroll
    for (int i = 0; i < 3; ++i) {
        ab[i] = smem_u32(&s_mbar[i]);
        mm[i] = smem_u32(&s_mbar[3 + i]);
    }
    const uint32_t sbar = smem_u32(&s_mbar[6]);
    const uint32_t eb   = smem_u32(&s_mbar[7]);
    float* epi = reinterpret_cast<float*>(dptr + I2S_EPI);   // [128][33]

    const int t0 = tq * 32;

    if (wid == 8) {
        if (tid == 256) {
            // prologue: chunks 0,1 (lt=0, cc=0 and 1)
            #pragma unroll
            for (int j = 0; j < 2; ++j) {
                uint32_t bufa = dbase + j * I2S_BUF;
                expect_tx(ab[j], 49152u);
                bulk_cp(bufa, (const char*)g_Wt + (size_t)(mt * 12 + j) * 16384, 16384u, ab[j]);
                bulk_cp(bufa + 16384,
                        (const char*)g_xt + (size_t)((b * H_ + t0) * 3 + j) * 32768,
                        32768u, ab[j]);
            }
            asm volatile("tcgen05.fence::after_thread_sync;" ::: "memory");
            #pragma unroll 1
            for (int gc = 0; gc < 96; ++gc) {
                const int lt = gc / 3, cc = gc % 3, m = gc % 3;
                const uint32_t sbuf = dbase + m * I2S_BUF;
                if (cc == 0 && lt >= 1) mbar_wait(eb, (lt - 1) & 1);
                mbar_wait(ab[m], (gc / 3) & 1);
                uint64_t dA = MKDESC(sbuf);
                uint64_t pb[2] = {MKDESC(sbuf + 16384), MKDESC(sbuf + 32768)};
                #pragma unroll
                for (int ps = 0; ps < 2; ++ps)
                    #pragma unroll
                    for (int ks = 0; ks < 4; ++ks) {
                        uint32_t en = (cc == 0 && ps == 0 && ks == 0) ? 0u : 1u;
                        mma_f16_ss(tmem, dA + ks * 2, pb[ps] + ks * 2, IDESC_F16, en);
                    }
                tc_commit(mm[m]);
                if (cc == 2) tc_commit(sbar);
                const int gcp = gc + 2;
                if (gcp < 96) {
                    const int mp = gcp % 3;
                    if (gcp >= 3) mbar_wait(mm[mp], (gcp / 3 - 1) & 1);
                    const int ltp = gcp / 3, ccp = gcp % 3;
                    uint32_t pbuf = dbase + mp * I2S_BUF;
                    expect_tx(ab[mp], 49152u);
                    bulk_cp(pbuf, (const char*)g_Wt + (size_t)(mt * 12 + ccp) * 16384,
                            16384u, ab[mp]);
                    bulk_cp(pbuf + 16384,
                            (const char*)g_xt +
                                (size_t)((b * H_ + t0 + ltp) * 3 + ccp) * 32768,
                            32768u, ab[mp]);
                }
            }
            mbar_wait(eb, 1u);   // epilogue of lt=31 done
        }
        __syncwarp();
        asm volatile("tcgen05.dealloc.cta_group::1.sync.aligned.b32 %0, %1;"
                     :: "r"(tmem), "r"(128u));
        asm volatile("tcgen05.relinquish_alloc_permit.cta_group::1.sync.aligned;");
    } else {
        const int sub = wid & 3;
        const int half = wid >> 2;
        #pragma unroll 1
        for (int lt = 0; lt < 32; ++lt) {
            mbar_wait(sbar, lt & 1);
            asm volatile("tcgen05.fence::after_thread_sync;" ::: "memory");
            float* dst = g_i2s + (((size_t)(b * H_ + t0 + lt)) * 6 + mt) * 16384;
            #pragma unroll 1
            for (int jq = 0; jq < 4; ++jq) {
                {
                    uint32_t dr[16];
                    LDTM_X16(dr, tmem + (uint32_t)(jq * 32 + half * 16));
                    asm volatile("tcgen05.wait::ld.sync.aligned;" ::: "memory");
                    int row = sub * 32 + lane;
                    int cb0 = half * 16;
                    #pragma unroll
                    for (int c2 = 0; c2 < 16; ++c2)
                        epi[row * 33 + cb0 + c2] = __uint_as_float(dr[c2]);
                }
                EPI_BAR();
                // coalesced write-out: [row][w] (scalar LDS — pitch 33 is not
                // 16B-aligned; float4 only for the gmem store)
                {
                    int row = tid >> 1, wh = tid & 1;
                    const float* s = &epi[row * 33 + wh * 16];
                    float v[16];
                    #pragma unroll
                    for (int k2 = 0; k2 < 16; ++k2) v[k2] = s[k2];
                    float* d = dst + (size_t)row * 128 + jq * 32 + wh * 16;
                    reinterpret_cast<float4*>(d)[0] = make_float4(v[0], v[1], v[2], v[3]);
                    reinterpret_cast<float4*>(d)[1] = make_float4(v[4], v[5], v[6], v[7]);
                    reinterpret_cast<float4*>(d)[2] = make_float4(v[8], v[9], v[10], v[11]);
                    reinterpret_cast<float4*>(d)[3] = make_float4(v[12], v[13], v[14], v[15]);
                }
                EPI_BAR();
            }
            asm volatile("tcgen05.fence::before_thread_sync;" ::: "memory");
            EPI_BAR();
            if (tid == 0) arrive_local(eb);
        }
    }
#endif  // TC05 (base-arch pass: empty body; fallback computes x in-loop)
}

// ===================== recurrent kernel =====================
#define UW_OFF 0                 // 9 x 16KB = 147456
#define RB_OFF 147456            // 2 buffers x 32KB (Bh|Bl)
#define REPI_OFF RB_OFF          // epilogue staging overlays buffers (safe: driver order)
#define RSTG_OFF (RB_OFF + 17408)
#define R_DSMEM (1024 + 147456 + 65536)

__global__ void __launch_bounds__(NTHREADS, 1)
lstm_persist(const float* __restrict__ bias, const float* __restrict__ ic,
             float* __restrict__ out)
{
    extern __shared__ __align__(16) char dsm[];
    const int tid = threadIdx.x;
    const int wid = tid >> 5;
    const int lane = tid & 31;
    const int mt = blockIdx.x;
    const int b  = blockIdx.y;

    const uint32_t raw = smem_u32(dsm);
    const uint32_t dbase = (raw + 1023u) & ~1023u;
    char* dptr = dsm + (dbase - raw);

    const int col0 = 4 * (wid & 7);
    const int w0 = lane;

    float creg[16];
    float breg[16];
    if (tid < 256) {
        #pragma unroll
        for (int i = 0; i < 4; ++i) {
            int co = mt * 32 + col0 + i;
            #pragma unroll
            for (int g = 0; g < 4; ++g) breg[i * 4 + g] = bias[g * NF_ + co];
            #pragma unroll
            for (int j = 0; j < 4; ++j)
                creg[i * 4 + j] = ic[co * W_ + (w0 + 32 * j)];
        }
    }
    const int cb_own = mt >> 1;

#if TC05
    __shared__ uint32_t s_tmem;
    __shared__ __align__(8) uint64_t s_mbar[7];   // ab0,ab1, mm0,mm1, sbar, eb, wb
    if (wid == 8) {
        asm volatile("tcgen05.alloc.cta_group::1.sync.aligned.shared::cta.b32 [%0], %1;"
                     :: "r"(smem_u32(&s_tmem)), "r"(128u) : "memory");
    }
    if (tid == 0) {
        #pragma unroll
        for (int i = 0; i < 7; ++i)
            asm volatile("mbarrier.init.shared.b64 [%0], 1;"
                         :: "r"(smem_u32(&s_mbar[i])) : "memory");
    }
    __syncthreads();
    const uint32_t tmem = s_tmem;
    const uint32_t ab[2] = {smem_u32(&s_mbar[0]), smem_u32(&s_mbar[1])};
    const uint32_t mm[2] = {smem_u32(&s_mbar[2]), smem_u32(&s_mbar[3])};
    const uint32_t sbar = smem_u32(&s_mbar[4]);
    const uint32_t eb   = smem_u32(&s_mbar[5]);
    const uint32_t wb   = smem_u32(&s_mbar[6]);
    float* epi = reinterpret_cast<float*>(dptr + REPI_OFF);      // [128][33]
    uint32_t* stg = reinterpret_cast<uint32_t*>(dptr + RSTG_OFF);// [32][33]
    const float* i2sb = g_i2s + ((size_t)(b * H_) * 6 + mt) * 16384;

    if (wid == 8) {
        // ================= driver warp =================
        if (tid == 256) {
            // one-time: U weights (9 x 16KB contiguous) into smem
            expect_tx(wb, 147456u);
            bulk_cp(dbase + UW_OFF, (const char*)g_Wt + (size_t)(mt * 12 + 3) * 16384,
                    147456u, wb);
            mbar_wait(wb, 0u);
            // prologue: h chunks 0,1 of step 0 (fill_bt slot 0)
            #pragma unroll
            for (int j = 0; j < 2; ++j) {
                expect_tx(ab[j], 32768u);
                bulk_cp(dbase + RB_OFF + j * 32768, g_bt[0][b][0][j], 32768u, ab[j]);
            }
            asm volatile("tcgen05.fence::after_thread_sync;" ::: "memory");

            #pragma unroll 1
            for (int gc = 0; gc < TOTR; ++gc) {
                const int t = gc / NCH, cc = gc % NCH;
                const int m = gc & 1;
                const uint32_t sbuf = dbase + RB_OFF + m * 32768;

                mbar_wait(ab[m], (gc >> 1) & 1);

                uint64_t dA = MKDESC(dbase + UW_OFF + cc * 16384);
                uint64_t pb[2] = {MKDESC(sbuf), MKDESC(sbuf + 16384)};
                #pragma unroll
                for (int ps = 0; ps < 2; ++ps)
                    #pragma unroll
                    for (int ks = 0; ks < 4; ++ks) {
                        uint32_t en = (cc == 0 && ps == 0 && ks == 0) ? 0u : 1u;
                        mma_f16_ss(tmem, dA + ks * 2, pb[ps] + ks * 2, IDESC_F16, en);
                    }
                tc_commit(mm[m]);

                if (cc <= NCH - 3) {
                    // within-step prefetch (h tiles of this step: parity slot t&1)
                    const int gcp = gc + 2;
                    const int mp = gcp & 1;
                    mbar_wait(mm[mp], ((gcp >> 1) - 1) & 1);
                    const int q = cc + 2;
                    expect_tx(ab[mp], 32768u);
                    bulk_cp(dbase + RB_OFF + mp * 32768,
                            g_bt[t & 1][b][q / 3][q % 3], 32768u, ab[mp]);
                } else if (cc == NCH - 1) {
                    tc_commit(sbar);
                    if (t + 1 < H_) {
                        const int tp = t + 1;
                        // h(t) published by all CTAs (also gates TMEM + buffer reuse
                        // against the running epilogue, which overlays the buffers)
                        while (g_gen < (unsigned)tp) { __nanosleep(64); }
                        __threadfence();
                        #pragma unroll
                        for (int j = 0; j < 2; ++j) {
                            const int gcp = tp * NCH + j;
                            const int mp = gcp & 1;
                            mbar_wait(mm[mp], ((gcp >> 1) - 1) & 1);
                            expect_tx(ab[mp], 32768u);
                            bulk_cp(dbase + RB_OFF + mp * 32768,
                                    g_bt[tp & 1][b][0][j], 32768u, ab[mp]);
                        }
                    }
                }
            }
            mbar_wait(eb, 0u);   // final epilogue drained TMEM
        }
        __syncwarp();
        asm volatile("tcgen05.dealloc.cta_group::1.sync.aligned.b32 %0, %1;"
                     :: "r"(tmem), "r"(128u));
        asm volatile("tcgen05.relinquish_alloc_permit.cta_group::1.sync.aligned;");
    } else {
        // ================= epilogue warps (0..7) =================
        const int sub = wid & 3;
        const int half = wid >> 2;
        const uint32_t hbase = (uint32_t)((mt & 1) * 64);
        #pragma unroll 1
        for (int t = 0; t < H_; ++t) {
            const int p = t & 1;
            mbar_wait(sbar, t & 1);
            asm volatile("tcgen05.fence::after_thread_sync;" ::: "memory");

            char* btn0 = g_bt[p ^ 1][b][0][cb_own];
            char* btn1 = g_bt[p ^ 1][b][1][cb_own];
            char* btn2 = g_bt[p ^ 1][b][2][cb_own];
            const float* i2st = i2sb + (size_t)t * 6 * 16384;

            #pragma unroll 1
            for (int jq = 0; jq < 4; ++jq) {
                {
                    uint32_t dr[16];
                    LDTM_X16(dr, tmem + (uint32_t)(jq * 32 + half * 16));
                    asm volatile("tcgen05.wait::ld.sync.aligned;" ::: "memory");
                    int row = sub * 32 + lane;
                    int cb0 = half * 16;
                    #pragma unroll
                    for (int c2 = 0; c2 < 16; ++c2)
                        epi[row * 33 + cb0 + c2] = __uint_as_float(dr[c2]);
                }
                EPI_BAR();
                {
                    int w = jq * 32 + w0;
                    #pragma unroll
                    for (int i = 0; i < 4; ++i) {
                        int co_l = col0 + i;
                        int co = mt * 32 + co_l;
                        float gv[4];
                        #pragma unroll
                        for (int g = 0; g < 4; ++g) {
                            int rr = co_l * 4 + g;
                            gv[g] = epi[rr * 33 + w0] +
                                    __ldg(i2st + (size_t)rr * 128 + w) + breg[i * 4 + g];
                        }
                        float ov = __saturatef(fmaf(0.2f, gv[0], 0.5f));
                        float fv = __saturatef(fmaf(0.2f, gv[1], 0.5f));
                        float iv = __saturatef(fmaf(0.2f, gv[2], 0.5f));
                        float cn = fv * creg[i * 4 + jq] + iv * fast_tanh(gv[3]);
                        creg[i * 4 + jq] = cn;
                        float hn = ov * fast_tanh(cn);
                        out[((size_t)(b * NF_ + co) * H_ + t) * W_ + w] = hn;
                        __half hh_ = __float2half_rn(hn);
                        __half hl_ = __float2half_rn(hn - __half2float(hh_));
                        stg[w0 * 33 + co_l] =
                            (uint32_t)__half_as_ushort(hh_) |
                            ((uint32_t)__half_as_ushort(hl_) << 16);
                    }
                }
                EPI_BAR();
                if (tid < 128) {
                    int r_off = tid >> 2;
                    int tpos = tid & 3;
                    int w2 = jq * 32 + r_off;
                    uint32_t u[8];
                    #pragma unroll
                    for (int k2 = 0; k2 < 8; ++k2)
                        u[k2] = stg[r_off * 33 + tpos * 8 + k2];
                    uint32_t hiw[4], low[4];
                    #pragma unroll
                    for (int m2 = 0; m2 < 4; ++m2) {
                        hiw[m2] = __byte_perm(u[2 * m2], u[2 * m2 + 1], 0x5410);
                        low[m2] = __byte_perm(u[2 * m2], u[2 * m2 + 1], 0x7632);
                    }
                    uint4 hv = make_uint4(hiw[0], hiw[1], hiw[2], hiw[3]);
                    uint4 lv = make_uint4(low[0], low[1], low[2], low[3]);
                    uint32_t base2 = hbase + (uint32_t)(tpos * 16);
                    if (w2 < 127) {
                        uint32_t off = SW128((uint32_t)((w2 + 1) * 128) + base2);
                        *(uint4*)(btn0 + off) = hv;
                        *(uint4*)(btn0 + 16384 + off) = lv;
                    }
                    {
                        uint32_t off = SW128((uint32_t)(w2 * 128) + base2);
                        *(uint4*)(btn1 + off) = hv;
                        *(uint4*)(btn1 + 16384 + off) = lv;
                    }
                    if (w2 > 0) {
                        uint32_t off = SW128((uint32_t)((w2 - 1) * 128) + base2);
                        *(uint4*)(btn2 + off) = hv;
                        *(uint4*)(btn2 + 16384 + off) = lv;
                    }
                }
                EPI_BAR();
            }

            asm volatile("tcgen05.fence::before_thread_sync;" ::: "memory");
            __threadfence();
            EPI_BAR();
            if (tid == 0) {
                if (t == H_ - 1) arrive_local(eb);
                unsigned prev = atomicAdd((unsigned*)&g_cnt, 1u);
                if (prev == GRIDN - 1u) {
                    g_cnt = 0;
                    __threadfence();
                    g_gen = (t == H_ - 1) ? 0u : (unsigned)(t + 1);
                }
            }
        }
    }
#else
    // ---------- fallback (base-arch pass; never selected when sm_103a cubin exists) ----------
    grid_sync();
    for (int t = 0; t < H_; ++t) {
        const int p = t & 1;
        if (tid < 256) {
            #pragma unroll 1
            for (int i = 0; i < 4; ++i) {
                int co_l = col0 + i;
                int co = mt * 32 + co_l;
                #pragma unroll 1
                for (int j = 0; j < 4; ++j) {
                    int w = w0 + 32 * j;
                    float acc[4] = {breg[i*4+0], breg[i*4+1], breg[i*4+2], breg[i*4+3]};
                    for (int k = 0; k < KALL; ++k) {
                        int cc = k >> 6, kl = k & 63;
                        float a;
                        if (k < C_) {
                            size_t tb2 = (size_t)((b * H_ + t) * 3 + cc) * 16384;
                            uint32_t swoff = SW128((uint32_t)(w * 128 + kl * 2));
                            a = __half2float(*(__half*)((char*)(g_xt + tb2) + swoff)) +
                                __half2float(*(__half*)((char*)(g_xt + tb2 + 8192) + swoff));
                        } else {
                            int q = cc - 3;
                            const char* tb3 = g_bt[p][b][q / 3][q % 3];
                            uint32_t swoff = SW128((uint32_t)(w * 128 + kl * 2));
                            a = __half2float(*(const __half*)(tb3 + swoff)) +
                                __half2float(*(const __half*)(tb3 + 16384 + swoff));
                        }
                        #pragma unroll
                        for (int g = 0; g < 4; ++g)
                            acc[g] = fmaf(g_Wf[(size_t)((mt*32+co_l)*4+g) * KALL + k], a, acc[g]);
                    }
                    float ov = __saturatef(fmaf(0.2f, acc[0], 0.5f));
                    float fv = __saturatef(fmaf(0.2f, acc[1], 0.5f));
                    float iv = __saturatef(fmaf(0.2f, acc[2], 0.5f));
                    float cn = fv * creg[i*4+j] + iv * tanhf(acc[3]);
                    creg[i*4+j] = cn;
                    float hn = ov * tanhf(cn);
                    out[((size_t)(b * NF_ + co) * H_ + t) * W_ + w] = hn;
                    __half vh = __float2half_rn(hn);
                    __half vl = __float2half_rn(hn - __half2float(vh));
                    #pragma unroll
                    for (int tau = 0; tau < 3; ++tau) {
                        int r = w + 1 - tau;
                        if (r >= 0 && r < 128) {
                            char* tb4 = g_bt[p ^ 1][b][tau][(mt * 32 + co_l) >> 6];
                            uint32_t off = SW128((uint32_t)(r * 128 + 2 * ((mt * 32 + co_l) & 63)));
                            *(__half*)(tb4 + off) = vh;
                            *(__half*)(tb4 + 16384 + off) = vl;
                        }
                    }
                }
            }
        }
        grid_sync();
    }
#endif
}

// ------------------- launch -------------------
extern "C" void kernel_launch(void* const* d_in, const int* in_sizes, int n_in,
                              void* d_out, int out_size) {
    const float* x  = (const float*)d_in[0];
    const float* Wf = (const float*)d_in[1];
    const float* Uf = (const float*)d_in[2];
    const float* bf = (const float*)d_in[3];
    const float* ih = (const float*)d_in[4];
    const float* ic = (const float*)d_in[5];
    float* out = (float*)d_out;

    cudaFuncSetAttribute(i2s_gemm, cudaFuncAttributeMaxDynamicSharedMemorySize, I2S_DSMEM);
    cudaFuncSetAttribute(lstm_persist, cudaFuncAttributeMaxDynamicSharedMemorySize, R_DSMEM);

    prep_weights<<<(6 * 128 * KALL + 255) / 256, 256>>>(Wf, Uf);
    prep_x<<<(B_ * H_ * 3 * 1024 + 255) / 256, 256>>>(x);
    zero_bt<<<592, 256>>>();
    fill_bt<<<(B_ * 3 * NF_ * W_ + 255) / 256, 256>>>(ih);

    dim3 gi(6, 16, 4);
    i2s_gemm<<<gi, NTHREADS, I2S_DSMEM>>>();

    dim3 grid(6, 16);
    lstm_persist<<<grid, NTHREADS, R_DSMEM>>>(bf, ic, out);
}

// round 17
// speedup vs baseline: 1.8157x; 1.8157x over previous
#include <cuda_runtime.h>
#include <cuda_fp16.h>
#include <cstdint>
#include <math.h>

#define B_   16
#define C_   192
#define H_   128
#define W_   128
#define NF_  192
#define O4_  768
#define KALL 768
#define NCHUNK 12
#define NTHREADS 288          // 8 epilogue warps + 1 driver warp
#define HW_  (H_ * W_)
#define GRIDN 96
#define TOTCH (H_ * NCHUNK)   // 1536

#if defined(__CUDA_ARCH_FEAT_SM103_ALL) || defined(__CUDA_ARCH_FEAT_SM100_ALL) || defined(__CUDA_ARCH_FEAT_SM101_ALL)
#define TC05 1
#else
#define TC05 0
#endif

// ---- persistent device scratch ----
__device__ __align__(1024) __half g_Wt[6 * NCHUNK * 8192];          // A tiles fp16 (16KB each)
__device__ __align__(1024) __half g_xt[(size_t)B_ * H_ * 3 * 8192]; // x B-tiles fp16 (16KB each)
__device__ float g_Wf[O4_ * KALL];                                   // fallback weights
// h B-tiles fp16, pre-swizzled, tau-shifted: [parity][b][tau][cb] 16KB
__device__ __align__(1024) char g_bt[2][B_][3][3][16384];
__device__ volatile unsigned g_cnt = 0;
__device__ volatile unsigned g_gen = 0;

// ------------------- helpers -------------------
static __device__ __forceinline__ uint32_t smem_u32(const void* p) {
    uint32_t a;
    asm("{ .reg .u64 t; cvta.to.shared.u64 t, %1; cvt.u32.u64 %0, t; }" : "=r"(a) : "l"(p));
    return a;
}
static __device__ __forceinline__ uint32_t pack_h2(__half a, __half b) {
    return (uint32_t)__half_as_ushort(a) | ((uint32_t)__half_as_ushort(b) << 16);
}
static __device__ __forceinline__ float fast_tanh(float x) {
    return 1.0f - 2.0f / (__expf(2.0f * x) + 1.0f);
}
#define SW128(o) ((uint32_t)(o) ^ ((((uint32_t)(o)) >> 3) & 0x70u))

static __device__ __forceinline__ void grid_sync() {   // fallback path only
    __syncthreads();
    if (threadIdx.x == 0) {
        __threadfence();
        unsigned gen = g_gen;
        if (atomicAdd((unsigned*)&g_cnt, 1u) == GRIDN - 1u) {
            g_cnt = 0;
            __threadfence();
            g_gen = gen + 1u;
        } else {
            while (g_gen == gen) { __nanosleep(32); }
            __threadfence();
        }
    }
    __syncthreads();
}

// ------------------- prep kernels -------------------
__global__ void prep_weights(const float* __restrict__ Wf, const float* __restrict__ Uf) {
    int idx = blockIdx.x * blockDim.x + threadIdx.x;
    if (idx >= 6 * 128 * KALL) return;
    int mt = idx / (128 * KALL);
    int m  = (idx / KALL) % 128;
    int k  = idx % KALL;
    int row = mt * 128 + m;
    int co = row >> 2, g = row & 3;
    int o = g * NF_ + co;
    int cc = k >> 6, kl = k & 63;
    float v;
    if (k < C_) {
        v = Wf[o * C_ + k];
        if ((o < 64 && k >= 64) || (o >= 64 && o < 128 && k >= 128)) v = 0.0f;
    } else {
        int q = cc - 3;
        int tau = q / 3;
        int cb = q - 3 * tau;
        int c = cb * 64 + kl;
        v = Uf[(o * NF_ + c) * 3 + tau];
    }
    g_Wf[row * KALL + k] = v;
    __half vh = __float2half_rn(v);
    size_t tile_base = (size_t)(mt * NCHUNK + cc) * 8192;
    uint32_t swoff = SW128((uint32_t)(m * 128 + kl * 2));
    *(__half*)((char*)(g_Wt + tile_base) + swoff) = vh;
}

__global__ void prep_x(const float* __restrict__ x) {
    int id = blockIdx.x * blockDim.x + threadIdx.x;
    if (id >= B_ * H_ * 3 * 1024) return;
    int tile = id >> 10;
    int inner = id & 1023;
    int oct = inner >> 7;
    int w = inner & 127;
    int cc = tile % 3;
    int t = (tile / 3) % H_;
    int b = tile / (3 * H_);
    __half hh[8];
    #pragma unroll
    for (int j = 0; j < 8; ++j) {
        int c = cc * 64 + oct * 8 + j;
        hh[j] = __float2half_rn(x[((size_t)(b * C_ + c) * H_ + t) * W_ + w]);
    }
    size_t tb = (size_t)tile * 8192;
    uint32_t swoff = SW128((uint32_t)(w * 128 + oct * 16));
    *(uint4*)((char*)(g_xt + tb) + swoff) =
        make_uint4(pack_h2(hh[0], hh[1]), pack_h2(hh[2], hh[3]),
                   pack_h2(hh[4], hh[5]), pack_h2(hh[6], hh[7]));
}

__global__ void zero_bt() {
    size_t n = sizeof(g_bt) / 16;
    uint4* p = reinterpret_cast<uint4*>(&g_bt[0][0][0][0][0]);
    size_t gidx = (size_t)blockIdx.x * blockDim.x + threadIdx.x;
    for (size_t i = gidx; i < n; i += (size_t)gridDim.x * blockDim.x)
        p[i] = make_uint4(0, 0, 0, 0);
    if (gidx == 0) { g_cnt = 0; g_gen = 0; }
}

// fill parity-0 payload from init_h; guards stay zero
__global__ void fill_bt(const float* __restrict__ ih) {
    int idx = blockIdx.x * blockDim.x + threadIdx.x;
    if (idx >= B_ * 3 * NF_ * W_) return;
    int w = idx & 127;
    int c = (idx >> 7) % NF_;
    int tau = (idx >> 7) / NF_ % 3;
    int b = idx / (3 * NF_ * W_);
    int r = w + 1 - tau;
    if (r < 0 || r >= 128) return;
    __half vh = __float2half_rn(ih[c * W_ + w]);
    int cb = c >> 6;
    char* tbase = g_bt[0][b][tau][cb];
    uint32_t off = SW128((uint32_t)(r * 128 + 2 * (c & 63)));
    *(__half*)(tbase + off) = vh;
}

// ------------------- TC05 machinery -------------------
#if TC05
static __device__ __forceinline__ void mbar_wait(uint32_t mbar, uint32_t parity) {
    asm volatile(
        "{\n\t.reg .pred P;\n\t"
        "WL_%=:\n\t"
        "mbarrier.try_wait.parity.acquire.cta.shared::cta.b64 P, [%0], %1, 0x989680;\n\t"
        "@P bra.uni WD_%=;\n\t"
        "bra.uni WL_%=;\n\t"
        "WD_%=:\n\t}"
        :: "r"(mbar), "r"(parity) : "memory");
}
static __device__ __forceinline__ void mma_f16_ss(uint32_t d, uint64_t da, uint64_t db,
                                                  uint32_t idesc, uint32_t en) {
    asm volatile(
        "{\n\t.reg .pred p;\n\t"
        "setp.ne.u32 p, %4, 0;\n\t"
        "tcgen05.mma.cta_group::1.kind::f16 [%0], %1, %2, %3, {%5, %5, %5, %5}, p;\n\t"
        "}"
        :: "r"(d), "l"(da), "l"(db), "r"(idesc), "r"(en), "r"(0u) : "memory");
}
static __device__ __forceinline__ void tc_commit(uint32_t mbar) {
    asm volatile("tcgen05.commit.cta_group::1.mbarrier::arrive::one.shared::cluster.b64 [%0];"
                 :: "r"(mbar) : "memory");
}
static __device__ __forceinline__ void bulk_cp(uint32_t dst, const void* src, uint32_t bytes,
                                               uint32_t mbar) {
    asm volatile(
        "cp.async.bulk.shared::cluster.global.mbarrier::complete_tx::bytes [%0], [%1], %2, [%3];"
        :: "r"(dst), "l"(src), "r"(bytes), "r"(mbar) : "memory");
}
static __device__ __forceinline__ void expect_tx(uint32_t mbar, uint32_t bytes) {
    asm volatile("mbarrier.arrive.expect_tx.shared.b64 _, [%0], %1;"
                 :: "r"(mbar), "r"(bytes) : "memory");
}
#define LDTM_X16(r, addr) \
    asm volatile( \
        "tcgen05.ld.sync.aligned.32x32b.x16.b32 " \
        "{%0, %1, %2, %3, %4, %5, %6, %7, " \
        " %8, %9, %10, %11, %12, %13, %14, %15}, [%16];" \
        : "=r"((r)[0]),  "=r"((r)[1]),  "=r"((r)[2]),  "=r"((r)[3]), \
          "=r"((r)[4]),  "=r"((r)[5]),  "=r"((r)[6]),  "=r"((r)[7]), \
          "=r"((r)[8]),  "=r"((r)[9]),  "=r"((r)[10]), "=r"((r)[11]), \
          "=r"((r)[12]), "=r"((r)[13]), "=r"((r)[14]), "=r"((r)[15]) \
        : "r"(addr))

static constexpr uint64_t DESC_BASE_SW128 =
    (uint64_t(2) << 61) | (uint64_t(1) << 46) | (uint64_t(64) << 32) | (uint64_t(1) << 16);
#define MKDESC(a) (DESC_BASE_SW128 | ((uint64_t)(((uint32_t)(a)) >> 4) & 0x3FFFull))
#define IDESC_F16 ((1u << 4) | (16u << 17) | (8u << 24))
#endif

#define T_AH 0
#define T_BH 16384
#define BUF_SZ 32768                  // A 16K + B 16K
#define EPI_OFF (3 * BUF_SZ)          // gates staging, pitch 33 floats (16896 B)
#define STG_OFF (3 * BUF_SZ + 17408)  // h staging, 32x33 u32 (4224 B)
#define DSMEM  (1024 + 3 * BUF_SZ + 32768)
#define EPI_BAR() asm volatile("bar.sync 1, 256;" ::: "memory")

// ------------------- persistent kernel -------------------
__global__ void __launch_bounds__(NTHREADS, 1)
lstm_persist(const float* __restrict__ bias, const float* __restrict__ ic,
             float* __restrict__ out)
{
    extern __shared__ __align__(16) char dsm[];
    const int tid = threadIdx.x;
    const int wid = tid >> 5;
    const int lane = tid & 31;
    const int mt = blockIdx.x;
    const int b  = blockIdx.y;

    const uint32_t raw = smem_u32(dsm);
    const uint32_t dbase = (raw + 1023u) & ~1023u;
    char* dptr = dsm + (dbase - raw);

    const int col0 = 4 * (wid & 7);
    const int w0 = lane;

    float creg[16];
    float breg[16];
    if (tid < 256) {
        #pragma unroll
        for (int i = 0; i < 4; ++i) {
            int co = mt * 32 + col0 + i;
            #pragma unroll
            for (int g = 0; g < 4; ++g) breg[i * 4 + g] = bias[g * NF_ + co];
            #pragma unroll
            for (int j = 0; j < 4; ++j)
                creg[i * 4 + j] = ic[co * W_ + (w0 + 32 * j)];
        }
    }
    const int cb_own = mt >> 1;

#if TC05
    __shared__ uint32_t s_tmem;
    __shared__ __align__(8) uint64_t s_mbar[9];   // ab0..2, mm0..2, sbar, eb0, eb1
    if (wid == 8) {
        asm volatile("tcgen05.alloc.cta_group::1.sync.aligned.shared::cta.b32 [%0], %1;"
                     :: "r"(smem_u32(&s_tmem)), "r"(256u) : "memory");
    }
    if (tid == 0) {
        #pragma unroll
        for (int i = 0; i < 9; ++i)
            asm volatile("mbarrier.init.shared.b64 [%0], 1;"
                         :: "r"(smem_u32(&s_mbar[i])) : "memory");
    }
    __syncthreads();
    const uint32_t tmem = s_tmem;
    uint32_t ab[3], mm[3];
    #pragma unroll
    for (int i = 0; i < 3; ++i) {
        ab[i] = smem_u32(&s_mbar[i]);
        mm[i] = smem_u32(&s_mbar[3 + i]);
    }
    const uint32_t sbar = smem_u32(&s_mbar[6]);
    const uint32_t eb[2] = {smem_u32(&s_mbar[7]), smem_u32(&s_mbar[8])};
    float* epi = reinterpret_cast<float*>(dptr + EPI_OFF);     // [128][33] floats
    uint32_t* stg = reinterpret_cast<uint32_t*>(dptr + STG_OFF); // [32][33] u32 (hi only)

    if (wid == 8) {
        // ================= driver warp =================
        if (tid == 256) {
            #pragma unroll
            for (int g0 = 0; g0 < 2; ++g0) {
                expect_tx(ab[g0], 32768u);
                bulk_cp(dbase + g0 * BUF_SZ + T_AH,
                        (const char*)g_Wt + (size_t)(mt * NCHUNK + g0) * 16384, 16384u, ab[g0]);
                bulk_cp(dbase + g0 * BUF_SZ + T_BH,
                        (const char*)g_xt + (size_t)(b * H_ * 3 + g0) * 16384, 16384u, ab[g0]);
            }
            asm volatile("tcgen05.fence::after_thread_sync;" ::: "memory");

            #pragma unroll 1
            for (int gc = 0; gc < TOTCH; ++gc) {
                const int t = gc / NCHUNK, cc = gc % NCHUNK;
                const int m = gc % 3;
                const uint32_t sbuf = dbase + m * BUF_SZ;
                const uint32_t doff = (uint32_t)(t & 1) * 128u;

                if (cc == 0 && t >= 2)
                    mbar_wait(eb[t & 1], ((t >> 1) - 1) & 1);

                mbar_wait(ab[m], (gc / 3) & 1);

                uint64_t dAh = MKDESC(sbuf + T_AH);
                uint64_t dBh = MKDESC(sbuf + T_BH);
                #pragma unroll
                for (int ks = 0; ks < 4; ++ks) {
                    uint32_t en = (cc == 0 && ks == 0) ? 0u : 1u;
                    mma_f16_ss(tmem + doff, dAh + ks * 2, dBh + ks * 2, IDESC_F16, en);
                }
                tc_commit(mm[m]);
                if (cc == NCHUNK - 1) tc_commit(sbar);

                const int gcp = gc + 2;
                if (gcp < TOTCH) {
                    const int mp = gcp % 3;
                    if (gcp >= 3) mbar_wait(mm[mp], ((gcp / 3) - 1) & 1);
                    const int tp = gcp / NCHUNK, ccp = gcp % NCHUNK;
                    if (ccp == 3) {
                        while (g_gen < (unsigned)tp) { __nanosleep(64); }
                        __threadfence();
                    }
                    const uint32_t pbuf = dbase + mp * BUF_SZ;
                    expect_tx(ab[mp], 32768u);
                    bulk_cp(pbuf + T_AH,
                            (const char*)g_Wt + (size_t)(mt * NCHUNK + ccp) * 16384,
                            16384u, ab[mp]);
                    const char* bsrc;
                    if (ccp < 3) {
                        bsrc = (const char*)g_xt + (size_t)((b * H_ + tp) * 3 + ccp) * 16384;
                    } else {
                        const int q = ccp - 3;
                        bsrc = g_bt[tp & 1][b][q / 3][q % 3];
                    }
                    bulk_cp(pbuf + T_BH, bsrc, 16384u, ab[mp]);
                }
            }
            mbar_wait(eb[0], 1u);
            mbar_wait(eb[1], 1u);
        }
        __syncwarp();
        asm volatile("tcgen05.dealloc.cta_group::1.sync.aligned.b32 %0, %1;"
                     :: "r"(tmem), "r"(256u));
        asm volatile("tcgen05.relinquish_alloc_permit.cta_group::1.sync.aligned;");
    } else {
        // ================= epilogue warps (0..7) =================
        const int sub = wid & 3;
        const int half = wid >> 2;
        const uint32_t hbase = (uint32_t)((mt & 1) * 64);   // byte offset of our 32-ch seg
        #pragma unroll 1
        for (int t = 0; t < H_; ++t) {
            const int p = t & 1;
            const uint32_t doff = (uint32_t)p * 128u;

            mbar_wait(sbar, t & 1);
            asm volatile("tcgen05.fence::after_thread_sync;" ::: "memory");

            char* btn0 = g_bt[p ^ 1][b][0][cb_own];
            char* btn1 = g_bt[p ^ 1][b][1][cb_own];
            char* btn2 = g_bt[p ^ 1][b][2][cb_own];

            #pragma unroll 1
            for (int jq = 0; jq < 4; ++jq) {
                // ---- LDTM quarter ----
                {
                    uint32_t dr[16];
                    LDTM_X16(dr, tmem + doff + (uint32_t)(jq * 32 + half * 16));
                    asm volatile("tcgen05.wait::ld.sync.aligned;" ::: "memory");
                    int row = sub * 32 + lane;
                    int cb0 = half * 16;
                    #pragma unroll
                    for (int c2 = 0; c2 < 16; ++c2)
                        epi[row * 33 + cb0 + c2] = __uint_as_float(dr[c2]);
                }
                EPI_BAR();

                // ---- pointwise: (4 co, w = jq*32 + w0) ----
                {
                    int w = jq * 32 + w0;
                    #pragma unroll
                    for (int i = 0; i < 4; ++i) {
                        int co_l = col0 + i;
                        int co = mt * 32 + co_l;
                        float gv[4];
                        #pragma unroll
                        for (int g = 0; g < 4; ++g)
                            gv[g] = epi[(co_l * 4 + g) * 33 + w0] + breg[i * 4 + g];
                        float ov = __saturatef(fmaf(0.2f, gv[0], 0.5f));
                        float fv = __saturatef(fmaf(0.2f, gv[1], 0.5f));
                        float iv = __saturatef(fmaf(0.2f, gv[2], 0.5f));
                        float cn = fv * creg[i * 4 + jq] + iv * fast_tanh(gv[3]);
                        creg[i * 4 + jq] = cn;
                        float hn = ov * fast_tanh(cn);
                        out[((size_t)(b * NF_ + co) * H_ + t) * W_ + w] = hn;
                        stg[w0 * 33 + co_l] =
                            (uint32_t)__half_as_ushort(__float2half_rn(hn));
                    }
                }
                EPI_BAR();

                // ---- coalesced copy-out to the 3 tau-shifted h tiles ----
                if (tid < 128) {
                    int r_off = tid >> 2;        // 0..31  (w within quarter)
                    int tpos = tid & 3;          // 16B unit within 64B segment
                    int w2 = jq * 32 + r_off;
                    uint32_t u[8];
                    #pragma unroll
                    for (int k2 = 0; k2 < 8; ++k2)
                        u[k2] = stg[r_off * 33 + tpos * 8 + k2];
                    uint32_t hiw[4];
                    #pragma unroll
                    for (int m2 = 0; m2 < 4; ++m2)
                        hiw[m2] = __byte_perm(u[2 * m2], u[2 * m2 + 1], 0x5410);
                    uint4 hv = make_uint4(hiw[0], hiw[1], hiw[2], hiw[3]);
                    uint32_t base2 = hbase + (uint32_t)(tpos * 16);
                    if (w2 < 127) {   // tau=0: row w+1
                        *(uint4*)(btn0 + SW128((uint32_t)((w2 + 1) * 128) + base2)) = hv;
                    }
                    {                 // tau=1: row w
                        *(uint4*)(btn1 + SW128((uint32_t)(w2 * 128) + base2)) = hv;
                    }
                    if (w2 > 0) {     // tau=2: row w-1
                        *(uint4*)(btn2 + SW128((uint32_t)((w2 - 1) * 128) + base2)) = hv;
                    }
                }
                EPI_BAR();
            }

            asm volatile("tcgen05.fence::before_thread_sync;" ::: "memory");
            __threadfence();
            EPI_BAR();
            if (tid == 0) {
                asm volatile("mbarrier.arrive.shared.b64 _, [%0];" :: "r"(eb[p]) : "memory");
                unsigned prev = atomicAdd((unsigned*)&g_cnt, 1u);
                if (prev == GRIDN - 1u) {
                    g_cnt = 0;
                    __threadfence();
                    g_gen = (t == H_ - 1) ? 0u : (unsigned)(t + 1);
                }
            }
        }
    }
#else
    // ---------- fallback (base-arch pass; never selected when sm_103a cubin exists) ----------
    grid_sync();
    for (int t = 0; t < H_; ++t) {
        const int p = t & 1;
        if (tid < 256) {
            #pragma unroll 1
            for (int i = 0; i < 4; ++i) {
                int co_l = col0 + i;
                int co = mt * 32 + co_l;
                #pragma unroll 1
                for (int j = 0; j < 4; ++j) {
                    int w = w0 + 32 * j;
                    float acc[4] = {breg[i*4+0], breg[i*4+1], breg[i*4+2], breg[i*4+3]};
                    for (int k = 0; k < KALL; ++k) {
                        int cc = k >> 6, kl = k & 63;
                        float a;
                        if (k < C_) {
                            size_t tb2 = (size_t)((b * H_ + t) * 3 + cc) * 8192;
                            uint32_t swoff = SW128((uint32_t)(w * 128 + kl * 2));
                            a = __half2float(*(__half*)((char*)(g_xt + tb2) + swoff));
                        } else {
                            int q = cc - 3;
                            const char* tb3 = g_bt[p][b][q / 3][q % 3];
                            uint32_t swoff = SW128((uint32_t)(w * 128 + kl * 2));
                            a = __half2float(*(const __half*)(tb3 + swoff));
                        }
                        #pragma unroll
                        for (int g = 0; g < 4; ++g)
                            acc[g] = fmaf(g_Wf[(size_t)((mt*32+co_l)*4+g) * KALL + k], a, acc[g]);
                    }
                    float ov = __saturatef(fmaf(0.2f, acc[0], 0.5f));
                    float fv = __saturatef(fmaf(0.2f, acc[1], 0.5f));
                    float iv = __saturatef(fmaf(0.2f, acc[2], 0.5f));
                    float cn = fv * creg[i*4+j] + iv * tanhf(acc[3]);
                    creg[i*4+j] = cn;
                    float hn = ov * tanhf(cn);
                    out[((size_t)(b * NF_ + co) * H_ + t) * W_ + w] = hn;
                    __half vh = __float2half_rn(hn);
                    #pragma unroll
                    for (int tau = 0; tau < 3; ++tau) {
                        int r = w + 1 - tau;
                        if (r >= 0 && r < 128) {
                            char* tb4 = g_bt[p ^ 1][b][tau][(mt * 32 + co_l) >> 6];
                            uint32_t off = SW128((uint32_t)(r * 128 + 2 * ((mt * 32 + co_l) & 63)));
                            *(__half*)(tb4 + off) = vh;
                        }
                    }
                }
            }
        }
        grid_sync();
    }
#endif
}

// ------------------- launch -------------------
extern "C" void kernel_launch(void* const* d_in, const int* in_sizes, int n_in,
                              void* d_out, int out_size) {
    const float* x  = (const float*)d_in[0];
    const float* Wf = (const float*)d_in[1];
    const float* Uf = (const float*)d_in[2];
    const float* bf = (const float*)d_in[3];
    const float* ih = (const float*)d_in[4];
    const float* ic = (const float*)d_in[5];
    float* out = (float*)d_out;

    cudaFuncSetAttribute(lstm_persist, cudaFuncAttributeMaxDynamicSharedMemorySize, DSMEM);

    prep_weights<<<(6 * 128 * KALL + 255) / 256, 256>>>(Wf, Uf);
    prep_x<<<(B_ * H_ * 3 * 1024 + 255) / 256, 256>>>(x);
    zero_bt<<<592, 256>>>();
    fill_bt<<<(B_ * 3 * NF_ * W_ + 255) / 256, 256>>>(ih);

    dim3 grid(6, 16);
    lstm_persist<<<grid, NTHREADS, DSMEM>>>(bf, ic, out);
}